// round 16
// baseline (speedup 1.0000x reference)
#include <cuda_runtime.h>
#include <cuda_bf16.h>
#include <cuda_fp16.h>
#include <stdint.h>
#include <math.h>

#define BATCH 8
#define NPTS 2048
#define KNN 20
#define TOTPTS (BATCH*NPTS)
#define FEAT 512
#define EPS 1e-5f

// ---------------- scratch (device globals; no allocation allowed) ----------------
__device__ float g_xt0[TOTPTS*3];
__device__ float g_xx[TOTPTS];
__device__ unsigned g_key[(size_t)BATCH*NPTS*NPTS];     // exact monotone u32 keys
__device__ int   g_idx[TOTPTS*KNN];
__device__ float g_fcat[TOTPTS*FEAT];
__device__ float g_P1[TOTPTS*256];
__device__ float g_P2[TOTPTS*256];
__device__ __nv_bfloat16 g_fhi[TOTPTS*FEAT];
__device__ __nv_bfloat16 g_flo[TOTPTS*FEAT];
__device__ __half g_f16[TOTPTS*FEAT];                   // fp16 copy for conv5
__device__ __half g_w516[1024*FEAT];                    // fp16 w5
__device__ __nv_bfloat16 g_pwhi[512*128];               // stacked [W1; W2-W1] split hi
__device__ __nv_bfloat16 g_pwlo[512*128];               // ... lo
__device__ float g_pmax[16*BATCH*1024];
__device__ float g_psum[16*BATCH*1024];
__device__ float g_pooled[BATCH*2048];
__device__ float g_h1[2*BATCH*512];
__device__ float g_h2[2*BATCH*256];
__device__ float g_W[(40+10)*256];

__device__ __forceinline__ unsigned dist_key(float d){
    unsigned u = __float_as_uint(d);
    return (u & 0x80000000u) ? ~u : (u | 0x80000000u);
}

__device__ __forceinline__ uint32_t smem_u32(const void* p){
    uint32_t a;
    asm("{ .reg .u64 t; cvta.to.shared.u64 t, %1; cvt.u32.u64 %0, t; }" : "=r"(a) : "l"(p));
    return a;
}
__device__ __forceinline__ void ldm_x4(uint32_t* r, uint32_t addr){
    asm volatile("ldmatrix.sync.aligned.m8n8.x4.shared.b16 {%0,%1,%2,%3}, [%4];"
        : "=r"(r[0]), "=r"(r[1]), "=r"(r[2]), "=r"(r[3]) : "r"(addr));
}
__device__ __forceinline__ void mma_bf16(float* c, const uint32_t* a, const uint32_t* b){
    asm volatile("mma.sync.aligned.m16n8k16.row.col.f32.bf16.bf16.f32 "
        "{%0,%1,%2,%3}, {%4,%5,%6,%7}, {%8,%9}, {%0,%1,%2,%3};"
        : "+f"(c[0]), "+f"(c[1]), "+f"(c[2]), "+f"(c[3])
        : "r"(a[0]), "r"(a[1]), "r"(a[2]), "r"(a[3]), "r"(b[0]), "r"(b[1]));
}
__device__ __forceinline__ void mma_f16(float* c, const uint32_t* a, const uint32_t* b){
    asm volatile("mma.sync.aligned.m16n8k16.row.col.f32.f16.f16.f32 "
        "{%0,%1,%2,%3}, {%4,%5,%6,%7}, {%8,%9}, {%0,%1,%2,%3};"
        : "+f"(c[0]), "+f"(c[1]), "+f"(c[2]), "+f"(c[3])
        : "r"(a[0]), "r"(a[1]), "r"(a[2]), "r"(a[3]), "r"(b[0]), "r"(b[1]));
}

// ---------------- prep ----------------
__global__ void k_prep(const float* __restrict__ x){
    int t = blockIdx.x*256 + threadIdx.x;
    if (t >= TOTPTS) return;
    int b = t / NPTS, n = t % NPTS;
    #pragma unroll
    for (int c = 0; c < 3; c++)
        g_xt0[t*3+c] = x[((size_t)b*3+c)*NPTS + n];
}

// ---------------- squared norms (layer 0 only) ----------------
__global__ void k_sqnorm0(){
    int t = blockIdx.x*256 + threadIdx.x;
    if (t >= TOTPTS) return;
    const float* r = g_xt0 + (size_t)t*3;
    g_xx[t] = r[0]*r[0] + r[1]*r[1] + r[2]*r[2];
}

// ---------------- dist layer0 (C=3): exact fp32 ----------------
__global__ void k_dist_small(){
    int b = blockIdx.z;
    const float* Xb  = g_xt0 + (size_t)b*NPTS*3;
    const float* xxb = g_xx + b*NPTS;
    unsigned* Db = g_key + (size_t)b*NPTS*NPTS;

    __shared__ float As[4][68];
    __shared__ float Bs[4][68];
    int tx = threadIdx.x, ty = threadIdx.y, tid = ty*16 + tx;
    int row0 = blockIdx.y*64, col0 = blockIdx.x*64;
    float acc[4][4] = {};

    if (tid < 192){
        int m = tid / 3, k = tid % 3;
        As[k][m] = Xb[(size_t)(row0+m)*3 + k];
        Bs[k][m] = Xb[(size_t)(col0+m)*3 + k];
    }
    __syncthreads();
    #pragma unroll
    for (int k = 0; k < 3; k++){
        float av[4], bv[4];
        #pragma unroll
        for (int i = 0; i < 4; i++) av[i] = As[k][ty*4+i];
        #pragma unroll
        for (int j = 0; j < 4; j++) bv[j] = Bs[k][tx*4+j];
        #pragma unroll
        for (int i = 0; i < 4; i++)
            #pragma unroll
            for (int j = 0; j < 4; j++) acc[i][j] += av[i]*bv[j];
    }
    float xc[4];
    #pragma unroll
    for (int j = 0; j < 4; j++) xc[j] = xxb[col0 + tx*4 + j];
    #pragma unroll
    for (int i = 0; i < 4; i++){
        int r = row0 + ty*4 + i;
        float xr = xxb[r];
        unsigned kk[4];
        #pragma unroll
        for (int j = 0; j < 4; j++)
            kk[j] = dist_key(2.f*acc[i][j] - xr - xc[j]);
        *(uint4*)&Db[(size_t)r*NPTS + col0 + tx*4] = *(uint4*)kk;
    }
}

// ---------------- dist layers 1-3: bf16-split mma, triangle + mirror, reg prefetch ----------------
#define KC 32
#define ASTRIDE 40
__global__ void __launch_bounds__(256) k_dist_mma(int in_off, int C){
    __shared__ __align__(16) __nv_bfloat16 Ah[128*ASTRIDE];
    __shared__ __align__(16) __nv_bfloat16 Al[128*ASTRIDE];
    __shared__ __align__(16) __nv_bfloat16 Bh[128*ASTRIDE];
    __shared__ __align__(16) __nv_bfloat16 Bl[128*ASTRIDE];

    int tid = threadIdx.x, wid = tid >> 5, lane = tid & 31;
    int b = blockIdx.z;
    int u = blockIdx.x;
    int by = (int)((sqrtf(8.f*u + 1.f) - 1.f) * 0.5f);
    while ((by+1)*(by+2)/2 <= u) by++;
    while (by*(by+1)/2 > u) by--;
    int bx = u - by*(by+1)/2;
    int row0 = by*128, col0 = bx*128;
    int wm = wid >> 2, wn = wid & 3;

    float acc[4][4][4];
    #pragma unroll
    for (int mi = 0; mi < 4; mi++)
        #pragma unroll
        for (int ni = 0; ni < 4; ni++)
            #pragma unroll
            for (int c = 0; c < 4; c++) acc[mi][ni][c] = 0.f;

    int lr = tid >> 1, ls = tid & 1;
    const __nv_bfloat16* pAh = g_fhi + ((size_t)b*NPTS + row0 + lr)*FEAT + in_off + ls*16;
    const __nv_bfloat16* pAl = g_flo + ((size_t)b*NPTS + row0 + lr)*FEAT + in_off + ls*16;
    const __nv_bfloat16* pBh = g_fhi + ((size_t)b*NPTS + col0 + lr)*FEAT + in_off + ls*16;
    const __nv_bfloat16* pBl = g_flo + ((size_t)b*NPTS + col0 + lr)*FEAT + in_off + ls*16;
    uint4* dAh = (uint4*)&Ah[lr*ASTRIDE + ls*16];
    uint4* dAl = (uint4*)&Al[lr*ASTRIDE + ls*16];
    uint4* dBh = (uint4*)&Bh[lr*ASTRIDE + ls*16];
    uint4* dBl = (uint4*)&Bl[lr*ASTRIDE + ls*16];

    uint32_t ah_base = smem_u32(Ah);
    uint32_t al_base = smem_u32(Al);
    uint32_t bh_base = smem_u32(Bh);
    uint32_t bl_base = smem_u32(Bl);

    const uint4* s;
    s = (const uint4*)(pAh); dAh[0] = s[0]; dAh[1] = s[1];
    s = (const uint4*)(pAl); dAl[0] = s[0]; dAl[1] = s[1];
    s = (const uint4*)(pBh); dBh[0] = s[0]; dBh[1] = s[1];
    s = (const uint4*)(pBl); dBl[0] = s[0]; dBl[1] = s[1];
    __syncthreads();

    int T = C/KC;
    for (int kc = 0; kc < T; kc++){
        uint4 rf[8];
        if (kc+1 < T){
            s = (const uint4*)(pAh + (kc+1)*KC); rf[0] = s[0]; rf[1] = s[1];
            s = (const uint4*)(pAl + (kc+1)*KC); rf[2] = s[0]; rf[3] = s[1];
            s = (const uint4*)(pBh + (kc+1)*KC); rf[4] = s[0]; rf[5] = s[1];
            s = (const uint4*)(pBl + (kc+1)*KC); rf[6] = s[0]; rf[7] = s[1];
        }
        #pragma unroll
        for (int ks = 0; ks < 2; ks++){
            int kk = ks*16;
            int g = lane >> 3, r = lane & 7;
            uint32_t ahf[4][4], alf[4][4];
            #pragma unroll
            for (int mi = 0; mi < 4; mi++){
                int arow = wm*64 + mi*16 + (g & 1)*8 + r;
                uint32_t off = (uint32_t)(arow*ASTRIDE + kk + (g >> 1)*8)*2u;
                ldm_x4(ahf[mi], ah_base + off);
                ldm_x4(alf[mi], al_base + off);
            }
            uint32_t bhf[2][4], blf[2][4];
            #pragma unroll
            for (int pr = 0; pr < 2; pr++){
                int nrow = wn*32 + pr*16 + (g >> 1)*8 + r;
                uint32_t off = (uint32_t)(nrow*ASTRIDE + kk + (g & 1)*8)*2u;
                ldm_x4(bhf[pr], bh_base + off);
                ldm_x4(blf[pr], bl_base + off);
            }
            #pragma unroll
            for (int mi = 0; mi < 4; mi++)
                #pragma unroll
                for (int ni = 0; ni < 4; ni++){
                    const uint32_t* bh2 = &bhf[ni >> 1][(ni & 1)*2];
                    const uint32_t* bl2 = &blf[ni >> 1][(ni & 1)*2];
                    mma_bf16(acc[mi][ni], ahf[mi], bh2);
                    mma_bf16(acc[mi][ni], ahf[mi], bl2);
                    mma_bf16(acc[mi][ni], alf[mi], bh2);
                }
        }
        __syncthreads();
        if (kc+1 < T){
            dAh[0] = rf[0]; dAh[1] = rf[1];
            dAl[0] = rf[2]; dAl[1] = rf[3];
            dBh[0] = rf[4]; dBh[1] = rf[5];
            dBl[0] = rf[6]; dBl[1] = rf[7];
            __syncthreads();
        }
    }

    // epilogue: keys for tile + mirror
    const float* xxb = g_xx + b*NPTS;
    unsigned* Db = g_key + (size_t)b*NPTS*NPTS;
    int rq = lane >> 2, cq = 2*(lane & 3);
    #pragma unroll
    for (int mi = 0; mi < 4; mi++){
        int rl0 = wm*64 + mi*16 + rq;
        float xr0 = xxb[row0 + rl0], xr1 = xxb[row0 + rl0 + 8];
        #pragma unroll
        for (int ni = 0; ni < 4; ni++){
            int cl0 = wn*32 + ni*8 + cq;
            float xc0 = xxb[col0 + cl0], xc1 = xxb[col0 + cl0 + 1];
            float a00 = 2.f*acc[mi][ni][0], a01 = 2.f*acc[mi][ni][1];
            float a10 = 2.f*acc[mi][ni][2], a11 = 2.f*acc[mi][ni][3];
            uint2 t0 = make_uint2(dist_key(a00 - xr0 - xc0), dist_key(a01 - xr0 - xc1));
            uint2 t1 = make_uint2(dist_key(a10 - xr1 - xc0), dist_key(a11 - xr1 - xc1));
            *(uint2*)&Db[(size_t)(row0 + rl0    )*NPTS + col0 + cl0] = t0;
            *(uint2*)&Db[(size_t)(row0 + rl0 + 8)*NPTS + col0 + cl0] = t1;
            if (bx != by){
                Db[(size_t)(col0 + cl0    )*NPTS + row0 + rl0    ] = dist_key(a00 - xc0 - xr0);
                Db[(size_t)(col0 + cl0 + 1)*NPTS + row0 + rl0    ] = dist_key(a01 - xc1 - xr0);
                Db[(size_t)(col0 + cl0    )*NPTS + row0 + rl0 + 8] = dist_key(a10 - xc0 - xr1);
                Db[(size_t)(col0 + cl0 + 1)*NPTS + row0 + rl0 + 8] = dist_key(a11 - xc1 - xr1);
            }
        }
    }
}

// ---------------- single-warp suffix scan over 256 bins + bucket pick ----------------
__device__ __forceinline__ void radix_pick(const int* hist, int r, int* sh_b, int* sh_r){
    int lane = threadIdx.x;
    int loc[8]; int tot = 0;
    #pragma unroll
    for (int q = 0; q < 8; q++){ loc[q] = hist[lane*8 + q]; tot += loc[q]; }
    int s = tot;
    #pragma unroll
    for (int off = 1; off < 32; off <<= 1){
        int v = __shfl_down_sync(0xffffffffu, s, off);
        if (lane + off < 32) s += v;
    }
    int run = s - tot;
    #pragma unroll
    for (int q = 7; q >= 0; q--){
        run += loc[q];
        if (run >= r && run - loc[q] < r){ *sh_b = lane*8 + q; *sh_r = r - (run - loc[q]); }
    }
}

// ---------------- top-k=20: warp-aggregated histogram atomics, exact tie refine ----------------
#define TIE_CAP 256
__global__ void k_topk(){
    int i = blockIdx.x, b = blockIdx.y;
    const unsigned* row = g_key + ((size_t)b*NPTS + i)*NPTS;
    int tid = threadIdx.x, lane = tid & 31;

    __shared__ int hist0[256];
    __shared__ int hist1[256];
    __shared__ int sh_b0, sh_r0, sh_b1, sh_r1;
    __shared__ int sh_cnt, sh_tiecnt;
    __shared__ unsigned tie_key[TIE_CAP];
    __shared__ int      tie_idx[TIE_CAP];

    unsigned key[8];
    *(uint4*)(key)   = ((const uint4*)row)[tid];
    *(uint4*)(key+4) = ((const uint4*)row)[tid + 256];

    hist0[tid] = 0; hist1[tid] = 0;
    if (tid == 0){ sh_cnt = 0; sh_tiecnt = 0; }
    __syncthreads();

    // pass 0: bits [31:24], warp-aggregated
    #pragma unroll
    for (int q = 0; q < 8; q++){
        unsigned bin = key[q] >> 24;
        unsigned mm = __match_any_sync(0xffffffffu, bin);
        if (lane == __ffs(mm) - 1) atomicAdd(&hist0[bin], __popc(mm));
    }
    __syncthreads();
    if (tid < 32) radix_pick(hist0, KNN, &sh_b0, &sh_r0);
    __syncthreads();
    unsigned hi = (unsigned)sh_b0;

    // pass 1: bits [23:16] among matching high byte, warp-aggregated
    #pragma unroll
    for (int q = 0; q < 8; q++){
        bool c = (key[q] >> 24) == hi;
        unsigned v = c ? ((key[q] >> 16) & 255u) : 0xFFFFFFFFu;
        unsigned mm = __match_any_sync(0xffffffffu, v);
        if (c && lane == __ffs(mm) - 1) atomicAdd(&hist1[v], __popc(mm));
    }
    __syncthreads();
    if (tid < 32) radix_pick(hist1, sh_r0, &sh_b1, &sh_r1);
    __syncthreads();

    unsigned T16 = (hi << 8) | (unsigned)sh_b1;
    int need_eq = sh_r1;
    int* out = g_idx + ((size_t)b*NPTS + i)*KNN;

    // emit: ballot-aggregated counters (slot order irrelevant: set semantics downstream)
    #pragma unroll
    for (int q = 0; q < 8; q++){
        unsigned k = key[q];
        unsigned t16 = k >> 16;
        int j = (q < 4) ? (tid*4 + q) : (1024 + tid*4 + q - 4);
        bool tk = t16 > T16;
        unsigned bm = __ballot_sync(0xffffffffu, tk);
        if (bm){
            int ldr = __ffs(bm) - 1;
            int base = 0;
            if (lane == ldr) base = atomicAdd(&sh_cnt, __popc(bm));
            base = __shfl_sync(0xffffffffu, base, ldr);
            if (tk) out[base + __popc(bm & ((1u << lane) - 1u))] = b*NPTS + j;
        }
        bool te = t16 == T16;
        unsigned bt = __ballot_sync(0xffffffffu, te);
        if (bt){
            int ldr = __ffs(bt) - 1;
            int base = 0;
            if (lane == ldr) base = atomicAdd(&sh_tiecnt, __popc(bt));
            base = __shfl_sync(0xffffffffu, base, ldr);
            if (te){
                int t = base + __popc(bt & ((1u << lane) - 1u));
                if (t < TIE_CAP){ tie_key[t] = k; tie_idx[t] = j; }
            }
        }
    }
    __syncthreads();
    if (tid == 0){
        int base = sh_cnt;
        int tc = sh_tiecnt; if (tc > TIE_CAP) tc = TIE_CAP;
        for (int q = 0; q < need_eq && base + q < KNN; q++){
            unsigned bk = 0; int bidx = 1 << 30, bu = -1;
            for (int u = 0; u < tc; u++){
                int vi = tie_idx[u];
                if (vi < 0) continue;
                unsigned vk = tie_key[u];
                if (bu < 0 || vk > bk || (vk == bk && vi < bidx)){
                    bk = vk; bidx = vi; bu = u;
                }
            }
            out[base + q] = b*NPTS + bidx;
            tie_idx[bu] = -1;
        }
    }
}

// ---------------- layer-0 projection (C=3): exact fp32 ----------------
__global__ void k_proj(int use0, int in_off, int C, int O, const float* __restrict__ w){
    int ldx = use0 ? 3 : FEAT;
    const float* X = use0 ? g_xt0 : (g_fcat + in_off);

    __shared__ float As[16][68];
    __shared__ float B1[16][68];
    __shared__ float B2[16][68];
    int tx = threadIdx.x, ty = threadIdx.y, tid = ty*16 + tx;
    int row0 = blockIdx.y*64, col0 = blockIdx.x*64;
    int lm = tid >> 2, lk = (tid & 3) * 4;
    float a1[4][4] = {}, a2[4][4] = {};

    for (int k0 = 0; k0 < C; k0 += 16){
        #pragma unroll
        for (int i = 0; i < 4; i++){
            int k = lk + i;
            float a = 0.f, b1 = 0.f, b2 = 0.f;
            if (k0 + k < C){
                a  = X[(size_t)(row0+lm)*ldx + k0 + k];
                b1 = w[(size_t)(col0+lm)*2*C + k0 + k];
                b2 = w[(size_t)(col0+lm)*2*C + C + k0 + k];
            }
            As[k][lm] = a; B1[k][lm] = b1; B2[k][lm] = b2;
        }
        __syncthreads();
        #pragma unroll
        for (int k = 0; k < 16; k++){
            float av[4], v1[4], v2[4];
            #pragma unroll
            for (int i = 0; i < 4; i++) av[i] = As[k][ty*4+i];
            #pragma unroll
            for (int j = 0; j < 4; j++){ v1[j] = B1[k][tx*4+j]; v2[j] = B2[k][tx*4+j]; }
            #pragma unroll
            for (int i = 0; i < 4; i++)
                #pragma unroll
                for (int j = 0; j < 4; j++){
                    a1[i][j] += av[i]*v1[j];
                    a2[i][j] += av[i]*v2[j];
                }
        }
        __syncthreads();
    }
    #pragma unroll
    for (int i = 0; i < 4; i++){
        int r = row0 + ty*4 + i;
        #pragma unroll
        for (int j = 0; j < 4; j++){
            int c = col0 + tx*4 + j;
            g_P1[(size_t)r*O + c] = a1[i][j];
            g_P2[(size_t)r*O + c] = a2[i][j] - a1[i][j];
        }
    }
}

// ---------------- stacked proj weights: rows [0,O)=W1, [O,2O)=W2-W1; bf16 split ----------------
__global__ void k_prepw(const float* __restrict__ w, int C, int O){
    int t = blockIdx.x*256 + threadIdx.x;
    if (t >= 2*O*C) return;
    int row = t / C, col = t % C;
    float v;
    if (row < O) v = w[(size_t)row*2*C + col];
    else         v = w[(size_t)(row-O)*2*C + C + col] - w[(size_t)(row-O)*2*C + col];
    __nv_bfloat16 h = __float2bfloat16(v);
    g_pwhi[(size_t)row*C + col] = h;
    g_pwlo[(size_t)row*C + col] = __float2bfloat16(v - __bfloat162float(h));
}

// ---------------- proj layers 1-3 via bf16-split mma: P = X @ [W1; W2-W1]^T ----------------
__global__ void __launch_bounds__(256) k_proj_mma(int in_off, int C, int O){
    __shared__ __align__(16) __nv_bfloat16 Ah[128*ASTRIDE];
    __shared__ __align__(16) __nv_bfloat16 Al[128*ASTRIDE];
    __shared__ __align__(16) __nv_bfloat16 Bh[128*ASTRIDE];
    __shared__ __align__(16) __nv_bfloat16 Bl[128*ASTRIDE];

    int tid = threadIdx.x, wid = tid >> 5, lane = tid & 31;
    int col0 = blockIdx.x*128;
    int row0 = blockIdx.y*128;
    int wm = wid >> 2, wn = wid & 3;

    float acc[4][4][4];
    #pragma unroll
    for (int mi = 0; mi < 4; mi++)
        #pragma unroll
        for (int ni = 0; ni < 4; ni++)
            #pragma unroll
            for (int c = 0; c < 4; c++) acc[mi][ni][c] = 0.f;

    int lr = tid >> 1, ls = tid & 1;
    const __nv_bfloat16* pAh = g_fhi + (size_t)(row0 + lr)*FEAT + in_off + ls*16;
    const __nv_bfloat16* pAl = g_flo + (size_t)(row0 + lr)*FEAT + in_off + ls*16;
    const __nv_bfloat16* pBh = g_pwhi + (size_t)(col0 + lr)*C + ls*16;
    const __nv_bfloat16* pBl = g_pwlo + (size_t)(col0 + lr)*C + ls*16;
    uint4* dAh = (uint4*)&Ah[lr*ASTRIDE + ls*16];
    uint4* dAl = (uint4*)&Al[lr*ASTRIDE + ls*16];
    uint4* dBh = (uint4*)&Bh[lr*ASTRIDE + ls*16];
    uint4* dBl = (uint4*)&Bl[lr*ASTRIDE + ls*16];

    uint32_t ah_base = smem_u32(Ah);
    uint32_t al_base = smem_u32(Al);
    uint32_t bh_base = smem_u32(Bh);
    uint32_t bl_base = smem_u32(Bl);

    const uint4* s;
    s = (const uint4*)(pAh); dAh[0] = s[0]; dAh[1] = s[1];
    s = (const uint4*)(pAl); dAl[0] = s[0]; dAl[1] = s[1];
    s = (const uint4*)(pBh); dBh[0] = s[0]; dBh[1] = s[1];
    s = (const uint4*)(pBl); dBl[0] = s[0]; dBl[1] = s[1];
    __syncthreads();

    int T = C/KC;
    for (int kc = 0; kc < T; kc++){
        uint4 rf[8];
        if (kc+1 < T){
            s = (const uint4*)(pAh + (kc+1)*KC); rf[0] = s[0]; rf[1] = s[1];
            s = (const uint4*)(pAl + (kc+1)*KC); rf[2] = s[0]; rf[3] = s[1];
            s = (const uint4*)(pBh + (kc+1)*KC); rf[4] = s[0]; rf[5] = s[1];
            s = (const uint4*)(pBl + (kc+1)*KC); rf[6] = s[0]; rf[7] = s[1];
        }
        #pragma unroll
        for (int ks = 0; ks < 2; ks++){
            int kk = ks*16;
            int g = lane >> 3, r = lane & 7;
            uint32_t ahf[4][4], alf[4][4];
            #pragma unroll
            for (int mi = 0; mi < 4; mi++){
                int arow = wm*64 + mi*16 + (g & 1)*8 + r;
                uint32_t off = (uint32_t)(arow*ASTRIDE + kk + (g >> 1)*8)*2u;
                ldm_x4(ahf[mi], ah_base + off);
                ldm_x4(alf[mi], al_base + off);
            }
            uint32_t bhf[2][4], blf[2][4];
            #pragma unroll
            for (int pr = 0; pr < 2; pr++){
                int nrow = wn*32 + pr*16 + (g >> 1)*8 + r;
                uint32_t off = (uint32_t)(nrow*ASTRIDE + kk + (g & 1)*8)*2u;
                ldm_x4(bhf[pr], bh_base + off);
                ldm_x4(blf[pr], bl_base + off);
            }
            #pragma unroll
            for (int mi = 0; mi < 4; mi++)
                #pragma unroll
                for (int ni = 0; ni < 4; ni++){
                    const uint32_t* bh2 = &bhf[ni >> 1][(ni & 1)*2];
                    const uint32_t* bl2 = &blf[ni >> 1][(ni & 1)*2];
                    mma_bf16(acc[mi][ni], ahf[mi], bh2);
                    mma_bf16(acc[mi][ni], ahf[mi], bl2);
                    mma_bf16(acc[mi][ni], alf[mi], bh2);
                }
        }
        __syncthreads();
        if (kc+1 < T){
            dAh[0] = rf[0]; dAh[1] = rf[1];
            dAl[0] = rf[2]; dAl[1] = rf[3];
            dBh[0] = rf[4]; dBh[1] = rf[5];
            dBl[0] = rf[6]; dBl[1] = rf[7];
            __syncthreads();
        }
    }

    // epilogue: scatter into g_P1 (cols < O) / g_P2 (cols >= O)
    int rq = lane >> 2, cq = 2*(lane & 3);
    #pragma unroll
    for (int mi = 0; mi < 4; mi++){
        int rl0 = wm*64 + mi*16 + rq;
        int pt0 = row0 + rl0, pt1 = pt0 + 8;
        #pragma unroll
        for (int ni = 0; ni < 4; ni++){
            int cg = col0 + wn*32 + ni*8 + cq;
            float* dst0;
            float* dst1;
            if (cg < O){
                dst0 = &g_P1[(size_t)pt0*O + cg];
                dst1 = &g_P1[(size_t)pt1*O + cg];
            } else {
                dst0 = &g_P2[(size_t)pt0*O + cg - O];
                dst1 = &g_P2[(size_t)pt1*O + cg - O];
            }
            *(float2*)dst0 = make_float2(acc[mi][ni][0], acc[mi][ni][1]);
            *(float2*)dst1 = make_float2(acc[mi][ni][2], acc[mi][ni][3]);
        }
    }
}

// ---------------- gather-max + BN + lrelu -> fcat + bf16 split + fp16 + fused sqnorm ----------------
__global__ void k_gathermax(int O, int out_off, const float* __restrict__ bnp){
    int pt = blockIdx.x;
    int o  = threadIdx.x;
    int lane = o & 31, wid = o >> 5;
    float g  = bnp[o], be = bnp[O+o], m = bnp[2*O+o], v = bnp[3*O+o];
    float sc = g * rsqrtf(v + EPS);
    float p2 = g_P2[(size_t)pt*O + o];

    __shared__ int id[KNN];
    __shared__ float ssum[8];
    if (o < KNN) id[o] = g_idx[(size_t)pt*KNN + o];
    __syncthreads();

    float mx = -3e38f, mn = 3e38f;
    #pragma unroll
    for (int j = 0; j < KNN; j++){
        float val = g_P1[(size_t)id[j]*O + o];
        mx = fmaxf(mx, val);
        mn = fminf(mn, val);
    }
    float chosen = (sc >= 0.f) ? mx : mn;
    float z = (chosen + p2 - m)*sc + be;
    z = z >= 0.f ? z : 0.2f*z;
    size_t idx = (size_t)pt*FEAT + out_off + o;
    g_fcat[idx] = z;
    __nv_bfloat16 h = __float2bfloat16(z);
    g_fhi[idx] = h;
    g_flo[idx] = __float2bfloat16(z - __bfloat162float(h));
    g_f16[idx] = __float2half(z);

    // fused squared-norm of this slice (next layer's xx)
    float zz = z*z;
    #pragma unroll
    for (int off = 16; off; off >>= 1) zz += __shfl_down_sync(0xffffffffu, zz, off);
    if (lane == 0) ssum[wid] = zz;
    __syncthreads();
    if (o == 0){
        float ssx = ssum[0];
        int nw = O >> 5;
        for (int w = 1; w < nw; w++) ssx += ssum[w];
        g_xx[pt] = ssx;
    }
}

// ---------------- fp16 of w5 ----------------
__global__ void k_splitw(const float* __restrict__ w5){
    int t = blockIdx.x*256 + threadIdx.x;
    if (t >= 1024*FEAT) return;
    g_w516[t] = __float2half(w5[t]);
}

// ---------------- conv5 via single-product fp16 mma, reg prefetch ----------------
__global__ void __launch_bounds__(256) k_conv5_mma(const float* __restrict__ bn5){
    __shared__ __align__(16) __half Ah[128*ASTRIDE];
    __shared__ __align__(16) __half Bh[128*ASTRIDE];
    __shared__ float red_mx[128][4];
    __shared__ float red_sm[128][4];

    int tid = threadIdx.x, wid = tid >> 5, lane = tid & 31;
    int b = blockIdx.z;
    int row0 = blockIdx.y*128, col0 = blockIdx.x*128;
    int wm = wid >> 2, wn = wid & 3;

    float acc[4][4][4];
    #pragma unroll
    for (int mi = 0; mi < 4; mi++)
        #pragma unroll
        for (int ni = 0; ni < 4; ni++)
            #pragma unroll
            for (int c = 0; c < 4; c++) acc[mi][ni][c] = 0.f;

    int lr = tid >> 1, ls = tid & 1;
    const __half* pA = g_w516 + (size_t)(row0 + lr)*FEAT + ls*16;
    const __half* pB = g_f16 + ((size_t)b*NPTS + col0 + lr)*FEAT + ls*16;
    uint4* dA = (uint4*)&Ah[lr*ASTRIDE + ls*16];
    uint4* dB = (uint4*)&Bh[lr*ASTRIDE + ls*16];

    uint32_t a_base = smem_u32(Ah);
    uint32_t b_base = smem_u32(Bh);

    const uint4* s;
    s = (const uint4*)(pA); dA[0] = s[0]; dA[1] = s[1];
    s = (const uint4*)(pB); dB[0] = s[0]; dB[1] = s[1];
    __syncthreads();

    const int T = FEAT/KC;   // 16
    for (int kc = 0; kc < T; kc++){
        uint4 rf[4];
        if (kc+1 < T){
            s = (const uint4*)(pA + (kc+1)*KC); rf[0] = s[0]; rf[1] = s[1];
            s = (const uint4*)(pB + (kc+1)*KC); rf[2] = s[0]; rf[3] = s[1];
        }
        #pragma unroll
        for (int ks = 0; ks < 2; ks++){
            int kk = ks*16;
            int g = lane >> 3, r = lane & 7;
            uint32_t af[4][4];
            #pragma unroll
            for (int mi = 0; mi < 4; mi++){
                int arow = wm*64 + mi*16 + (g & 1)*8 + r;
                uint32_t off = (uint32_t)(arow*ASTRIDE + kk + (g >> 1)*8)*2u;
                ldm_x4(af[mi], a_base + off);
            }
            uint32_t bf[2][4];
            #pragma unroll
            for (int pr = 0; pr < 2; pr++){
                int nrow = wn*32 + pr*16 + (g >> 1)*8 + r;
                uint32_t off = (uint32_t)(nrow*ASTRIDE + kk + (g & 1)*8)*2u;
                ldm_x4(bf[pr], b_base + off);
            }
            #pragma unroll
            for (int mi = 0; mi < 4; mi++)
                #pragma unroll
                for (int ni = 0; ni < 4; ni++)
                    mma_f16(acc[mi][ni], af[mi], &bf[ni >> 1][(ni & 1)*2]);
        }
        __syncthreads();
        if (kc+1 < T){
            dA[0] = rf[0]; dA[1] = rf[1];
            dB[0] = rf[2]; dB[1] = rf[3];
            __syncthreads();
        }
    }

    // epilogue: BN + lrelu, per-row max/sum over this block's 128 columns
    #pragma unroll
    for (int mi = 0; mi < 4; mi++){
        #pragma unroll
        for (int half = 0; half < 2; half++){
            int lrow = wm*64 + mi*16 + (lane >> 2) + half*8;
            int o = row0 + lrow;
            float g = bn5[o], be = bn5[1024+o], mm = bn5[2048+o], vv = bn5[3072+o];
            float sc = g * rsqrtf(vv + EPS);
            float mx = -3e38f, sm = 0.f;
            #pragma unroll
            for (int ni = 0; ni < 4; ni++){
                float z0 = (acc[mi][ni][half*2+0] - mm)*sc + be;
                z0 = z0 >= 0.f ? z0 : 0.2f*z0;
                float z1 = (acc[mi][ni][half*2+1] - mm)*sc + be;
                z1 = z1 >= 0.f ? z1 : 0.2f*z1;
                mx = fmaxf(mx, fmaxf(z0, z1)); sm += z0 + z1;
            }
            mx = fmaxf(mx, __shfl_xor_sync(0xffffffffu, mx, 1));
            sm += __shfl_xor_sync(0xffffffffu, sm, 1);
            mx = fmaxf(mx, __shfl_xor_sync(0xffffffffu, mx, 2));
            sm += __shfl_xor_sync(0xffffffffu, sm, 2);
            if ((lane & 3) == 0){
                red_mx[lrow][wn] = mx;
                red_sm[lrow][wn] = sm;
            }
        }
    }
    __syncthreads();
    if (tid < 128){
        float mx = red_mx[tid][0], sm = red_sm[tid][0];
        #pragma unroll
        for (int q = 1; q < 4; q++){
            mx = fmaxf(mx, red_mx[tid][q]);
            sm += red_sm[tid][q];
        }
        int idx = (blockIdx.x*BATCH + b)*1024 + row0 + tid;
        g_pmax[idx] = mx;
        g_psum[idx] = sm;
    }
}

// ---------------- reduce partials -> pooled [max, mean] ----------------
__global__ void k_poolreduce(){
    int t = blockIdx.x*256 + threadIdx.x;
    if (t >= BATCH*1024) return;
    int b = t / 1024, o = t % 1024;
    float mx = -3e38f, sm = 0.f;
    #pragma unroll
    for (int nb = 0; nb < 16; nb++){
        int idx = (nb*BATCH + b)*1024 + o;
        mx = fmaxf(mx, g_pmax[idx]);
        sm += g_psum[idx];
    }
    g_pooled[b*2048 + o]        = mx;
    g_pooled[b*2048 + 1024 + o] = sm * (1.0f/NPTS);
}

// ---------------- head layer 1 ----------------
__global__ void k_head1(const float* __restrict__ lw1o, const float* __restrict__ bn6o,
                        const float* __restrict__ lw1n, const float* __restrict__ bn6n){
    int gw = (blockIdx.x*blockDim.x + threadIdx.x) >> 5;
    int lane = threadIdx.x & 31;
    if (gw >= 2*BATCH*512) return;
    int h = gw / (BATCH*512), r = gw % (BATCH*512);
    int b = r / 512, o = r & 511;
    const float* w  = (h ? lw1n : lw1o) + (size_t)o*2048;
    const float* bp =  h ? bn6n : bn6o;
    const float* p  = g_pooled + b*2048;
    float s = 0.f;
    for (int c = lane; c < 2048; c += 32) s += p[c]*w[c];
    #pragma unroll
    for (int off = 16; off; off >>= 1) s += __shfl_down_sync(0xffffffffu, s, off);
    if (lane == 0){
        float z = (s - bp[1024+o]) * bp[o] * rsqrtf(bp[1536+o] + EPS) + bp[512+o];
        g_h1[gw] = z >= 0.f ? z : 0.2f*z;
    }
}

// ---------------- head layer 2 ----------------
__global__ void k_head2(const float* __restrict__ lw2o, const float* __restrict__ lb2o,
                        const float* __restrict__ bn7o,
                        const float* __restrict__ lw2n, const float* __restrict__ lb2n,
                        const float* __restrict__ bn7n){
    int gw = (blockIdx.x*blockDim.x + threadIdx.x) >> 5;
    int lane = threadIdx.x & 31;
    if (gw >= 2*BATCH*256) return;
    int h = gw / (BATCH*256), r = gw % (BATCH*256);
    int b = r / 256, o = r & 255;
    const float* w  = (h ? lw2n : lw2o) + (size_t)o*512;
    const float* lb =  h ? lb2n : lb2o;
    const float* bp =  h ? bn7n : bn7o;
    const float* hh = g_h1 + h*BATCH*512 + b*512;
    float s = 0.f;
    for (int c = lane; c < 512; c += 32) s += hh[c]*w[c];
    #pragma unroll
    for (int off = 16; off; off >>= 1) s += __shfl_down_sync(0xffffffffu, s, off);
    if (lane == 0){
        s += lb[o];
        float z = (s - bp[512+o]) * bp[o] * rsqrtf(bp[768+o] + EPS) + bp[256+o];
        g_h2[gw] = z >= 0.f ? z : 0.2f*z;
    }
}

// ---------------- attribute class-weight matrices ----------------
__global__ void k_attW(const float* __restrict__ old_att, const float* __restrict__ attwo,
                       const float* __restrict__ attbo,
                       const float* __restrict__ new_att, const float* __restrict__ attwn,
                       const float* __restrict__ attbn){
    int gw = (blockIdx.x*blockDim.x + threadIdx.x) >> 5;
    int lane = threadIdx.x & 31;
    if (gw >= 50*256) return;
    const float *att, *aw, *ab;
    int a, o;
    if (gw < 40*256){ a = gw / 256; o = gw & 255; att = old_att; aw = attwo; ab = attbo; }
    else { int g2 = gw - 40*256; a = g2 / 256; o = g2 & 255; att = new_att; aw = attwn; ab = attbn; }
    float s = 0.f;
    for (int c = lane; c < 300; c += 32) s += att[a*300+c]*aw[o*300+c];
    #pragma unroll
    for (int off = 16; off; off >>= 1) s += __shfl_down_sync(0xffffffffu, s, off);
    if (lane == 0) g_W[gw] = fmaxf(0.f, s + ab[o]);
}

// ---------------- final ----------------
__global__ void k_final(float* __restrict__ out){
    int gw = (blockIdx.x*blockDim.x + threadIdx.x) >> 5;
    int lane = threadIdx.x & 31;
    if (gw >= 400) return;
    int h, b, a;
    const float* Wb;
    if (gw < 320){ h = 0; b = gw / 40; a = gw % 40; Wb = g_W + a*256; }
    else { int t = gw - 320; h = 1; b = t / 10; a = t % 10; Wb = g_W + 40*256 + a*256; }
    const float* hh = g_h2 + h*BATCH*256 + b*256;
    float s = 0.f;
    for (int c = lane; c < 256; c += 32) s += hh[c]*Wb[c];
    #pragma unroll
    for (int off = 16; off; off >>= 1) s += __shfl_down_sync(0xffffffffu, s, off);
    if (lane == 0) out[gw] = s;
}

// ---------------- launch ----------------
extern "C" void kernel_launch(void* const* d_in, const int* in_sizes, int n_in,
                              void* d_out, int out_size){
    const float* x        = (const float*)d_in[0];
    const float* old_att  = (const float*)d_in[1];
    const float* new_att  = (const float*)d_in[2];
    const float* w1       = (const float*)d_in[3];
    const float* w2       = (const float*)d_in[4];
    const float* w3       = (const float*)d_in[5];
    const float* w4       = (const float*)d_in[6];
    const float* w5       = (const float*)d_in[7];
    const float* bn1      = (const float*)d_in[8];
    const float* bn2      = (const float*)d_in[9];
    const float* bn3      = (const float*)d_in[10];
    const float* bn4      = (const float*)d_in[11];
    const float* bn5      = (const float*)d_in[12];
    const float* lw1_old  = (const float*)d_in[13];
    const float* bn6_old  = (const float*)d_in[14];
    const float* lw2_old  = (const float*)d_in[15];
    const float* lb2_old  = (const float*)d_in[16];
    const float* bn7_old  = (const float*)d_in[17];
    const float* lw1_new  = (const float*)d_in[18];
    const float* bn6_new  = (const float*)d_in[19];
    const float* lw2_new  = (const float*)d_in[20];
    const float* lb2_new  = (const float*)d_in[21];
    const float* bn7_new  = (const float*)d_in[22];
    const float* attw_old = (const float*)d_in[23];
    const float* attb_old = (const float*)d_in[24];
    const float* attw_new = (const float*)d_in[25];
    const float* attb_new = (const float*)d_in[26];

    dim3 t16(16, 16);

    k_prep<<<(TOTPTS+255)/256, 256>>>(x);
    k_sqnorm0<<<TOTPTS/256, 256>>>();

    struct Layer { int use0, in_off, C, O, out_off; const float *w, *bn; };
    Layer L[4] = {
        {1,   0,   3,  64,   0, w1, bn1},
        {0,   0,  64,  64,  64, w2, bn2},
        {0,  64,  64, 128, 128, w3, bn3},
        {0, 128, 128, 256, 256, w4, bn4},
    };

    for (int l = 0; l < 4; l++){
        if (L[l].use0)
            k_dist_small<<<dim3(NPTS/64, NPTS/64, BATCH), t16>>>();
        else
            k_dist_mma<<<dim3(136, 1, BATCH), 256>>>(L[l].in_off, L[l].C);
        k_topk<<<dim3(NPTS, BATCH), 256>>>();
        if (L[l].use0){
            k_proj<<<dim3(L[l].O/64, TOTPTS/64), t16>>>(L[l].use0, L[l].in_off, L[l].C, L[l].O, L[l].w);
        } else {
            int C = L[l].C, O = L[l].O;
            k_prepw<<<(2*O*C + 255)/256, 256>>>(L[l].w, C, O);
            k_proj_mma<<<dim3(2*O/128, TOTPTS/128), 256>>>(L[l].in_off, C, O);
        }
        k_gathermax<<<TOTPTS, L[l].O>>>(L[l].O, L[l].out_off, L[l].bn);
    }

    k_splitw<<<(1024*FEAT)/256, 256>>>(w5);
    k_conv5_mma<<<dim3(NPTS/128, 1024/128, BATCH), 256>>>(bn5);
    k_poolreduce<<<(BATCH*1024 + 255)/256, 256>>>();
    k_head1<<<(2*BATCH*512*32)/256, 256>>>(lw1_old, bn6_old, lw1_new, bn6_new);
    k_head2<<<(2*BATCH*256*32)/256, 256>>>(lw2_old, lb2_old, bn7_old, lw2_new, lb2_new, bn7_new);
    k_attW<<<(50*256*32)/256, 256>>>(old_att, attw_old, attb_old, new_att, attw_new, attb_new);
    k_final<<<(400*32 + 255)/256, 256>>>((float*)d_out);
}

// round 17
// speedup vs baseline: 1.2298x; 1.2298x over previous
#include <cuda_runtime.h>
#include <cuda_bf16.h>
#include <cuda_fp16.h>
#include <stdint.h>
#include <math.h>

#define BATCH 8
#define NPTS 2048
#define KNN 20
#define TOTPTS (BATCH*NPTS)
#define FEAT 512
#define EPS 1e-5f

// ---------------- scratch (device globals; no allocation allowed) ----------------
__device__ float g_xt0[TOTPTS*3];
__device__ float g_xx[TOTPTS];
__device__ unsigned g_key[(size_t)BATCH*NPTS*NPTS];     // exact monotone u32 keys
__device__ int   g_idx[TOTPTS*KNN];
__device__ float g_fcat[TOTPTS*FEAT];
__device__ float g_P1[TOTPTS*256];
__device__ float g_P2[TOTPTS*256];
__device__ __nv_bfloat16 g_fhi[TOTPTS*FEAT];
__device__ __nv_bfloat16 g_flo[TOTPTS*FEAT];
__device__ __half g_f16[TOTPTS*FEAT];                   // fp16 copy for conv5
__device__ __half g_w516[1024*FEAT];                    // fp16 w5
__device__ __nv_bfloat16 g_pwhi[512*128];               // stacked [W1; W2-W1] split hi
__device__ __nv_bfloat16 g_pwlo[512*128];               // ... lo
__device__ float g_pmax[16*BATCH*1024];
__device__ float g_psum[16*BATCH*1024];
__device__ float g_pooled[BATCH*2048];
__device__ float g_h1[2*BATCH*512];
__device__ float g_h2[2*BATCH*256];
__device__ float g_W[(40+10)*256];

__device__ __forceinline__ unsigned dist_key(float d){
    unsigned u = __float_as_uint(d);
    return (u & 0x80000000u) ? ~u : (u | 0x80000000u);
}

__device__ __forceinline__ uint32_t smem_u32(const void* p){
    uint32_t a;
    asm("{ .reg .u64 t; cvta.to.shared.u64 t, %1; cvt.u32.u64 %0, t; }" : "=r"(a) : "l"(p));
    return a;
}
__device__ __forceinline__ void ldm_x4(uint32_t* r, uint32_t addr){
    asm volatile("ldmatrix.sync.aligned.m8n8.x4.shared.b16 {%0,%1,%2,%3}, [%4];"
        : "=r"(r[0]), "=r"(r[1]), "=r"(r[2]), "=r"(r[3]) : "r"(addr));
}
__device__ __forceinline__ void mma_bf16(float* c, const uint32_t* a, const uint32_t* b){
    asm volatile("mma.sync.aligned.m16n8k16.row.col.f32.bf16.bf16.f32 "
        "{%0,%1,%2,%3}, {%4,%5,%6,%7}, {%8,%9}, {%0,%1,%2,%3};"
        : "+f"(c[0]), "+f"(c[1]), "+f"(c[2]), "+f"(c[3])
        : "r"(a[0]), "r"(a[1]), "r"(a[2]), "r"(a[3]), "r"(b[0]), "r"(b[1]));
}
__device__ __forceinline__ void mma_f16(float* c, const uint32_t* a, const uint32_t* b){
    asm volatile("mma.sync.aligned.m16n8k16.row.col.f32.f16.f16.f32 "
        "{%0,%1,%2,%3}, {%4,%5,%6,%7}, {%8,%9}, {%0,%1,%2,%3};"
        : "+f"(c[0]), "+f"(c[1]), "+f"(c[2]), "+f"(c[3])
        : "r"(a[0]), "r"(a[1]), "r"(a[2]), "r"(a[3]), "r"(b[0]), "r"(b[1]));
}

// ---------------- prep: transpose + fused layer-0 squared norm ----------------
__global__ void k_prep(const float* __restrict__ x){
    int t = blockIdx.x*256 + threadIdx.x;
    if (t >= TOTPTS) return;
    int b = t / NPTS, n = t % NPTS;
    float v0 = x[((size_t)b*3+0)*NPTS + n];
    float v1 = x[((size_t)b*3+1)*NPTS + n];
    float v2 = x[((size_t)b*3+2)*NPTS + n];
    g_xt0[t*3+0] = v0;
    g_xt0[t*3+1] = v1;
    g_xt0[t*3+2] = v2;
    g_xx[t] = v0*v0 + v1*v1 + v2*v2;
}

// ---------------- dist layer0 (C=3): exact fp32 ----------------
__global__ void k_dist_small(){
    int b = blockIdx.z;
    const float* Xb  = g_xt0 + (size_t)b*NPTS*3;
    const float* xxb = g_xx + b*NPTS;
    unsigned* Db = g_key + (size_t)b*NPTS*NPTS;

    __shared__ float As[4][68];
    __shared__ float Bs[4][68];
    int tx = threadIdx.x, ty = threadIdx.y, tid = ty*16 + tx;
    int row0 = blockIdx.y*64, col0 = blockIdx.x*64;
    float acc[4][4] = {};

    if (tid < 192){
        int m = tid / 3, k = tid % 3;
        As[k][m] = Xb[(size_t)(row0+m)*3 + k];
        Bs[k][m] = Xb[(size_t)(col0+m)*3 + k];
    }
    __syncthreads();
    #pragma unroll
    for (int k = 0; k < 3; k++){
        float av[4], bv[4];
        #pragma unroll
        for (int i = 0; i < 4; i++) av[i] = As[k][ty*4+i];
        #pragma unroll
        for (int j = 0; j < 4; j++) bv[j] = Bs[k][tx*4+j];
        #pragma unroll
        for (int i = 0; i < 4; i++)
            #pragma unroll
            for (int j = 0; j < 4; j++) acc[i][j] += av[i]*bv[j];
    }
    float xc[4];
    #pragma unroll
    for (int j = 0; j < 4; j++) xc[j] = xxb[col0 + tx*4 + j];
    #pragma unroll
    for (int i = 0; i < 4; i++){
        int r = row0 + ty*4 + i;
        float xr = xxb[r];
        unsigned kk[4];
        #pragma unroll
        for (int j = 0; j < 4; j++)
            kk[j] = dist_key(2.f*acc[i][j] - xr - xc[j]);
        *(uint4*)&Db[(size_t)r*NPTS + col0 + tx*4] = *(uint4*)kk;
    }
}

// ---------------- dist layers 1-3: bf16-split mma, triangle + mirror, reg prefetch ----------------
#define KC 32
#define ASTRIDE 40
__global__ void __launch_bounds__(256) k_dist_mma(int in_off, int C){
    __shared__ __align__(16) __nv_bfloat16 Ah[128*ASTRIDE];
    __shared__ __align__(16) __nv_bfloat16 Al[128*ASTRIDE];
    __shared__ __align__(16) __nv_bfloat16 Bh[128*ASTRIDE];
    __shared__ __align__(16) __nv_bfloat16 Bl[128*ASTRIDE];

    int tid = threadIdx.x, wid = tid >> 5, lane = tid & 31;
    int b = blockIdx.z;
    int u = blockIdx.x;
    int by = (int)((sqrtf(8.f*u + 1.f) - 1.f) * 0.5f);
    while ((by+1)*(by+2)/2 <= u) by++;
    while (by*(by+1)/2 > u) by--;
    int bx = u - by*(by+1)/2;
    int row0 = by*128, col0 = bx*128;
    int wm = wid >> 2, wn = wid & 3;

    float acc[4][4][4];
    #pragma unroll
    for (int mi = 0; mi < 4; mi++)
        #pragma unroll
        for (int ni = 0; ni < 4; ni++)
            #pragma unroll
            for (int c = 0; c < 4; c++) acc[mi][ni][c] = 0.f;

    int lr = tid >> 1, ls = tid & 1;
    const __nv_bfloat16* pAh = g_fhi + ((size_t)b*NPTS + row0 + lr)*FEAT + in_off + ls*16;
    const __nv_bfloat16* pAl = g_flo + ((size_t)b*NPTS + row0 + lr)*FEAT + in_off + ls*16;
    const __nv_bfloat16* pBh = g_fhi + ((size_t)b*NPTS + col0 + lr)*FEAT + in_off + ls*16;
    const __nv_bfloat16* pBl = g_flo + ((size_t)b*NPTS + col0 + lr)*FEAT + in_off + ls*16;
    uint4* dAh = (uint4*)&Ah[lr*ASTRIDE + ls*16];
    uint4* dAl = (uint4*)&Al[lr*ASTRIDE + ls*16];
    uint4* dBh = (uint4*)&Bh[lr*ASTRIDE + ls*16];
    uint4* dBl = (uint4*)&Bl[lr*ASTRIDE + ls*16];

    uint32_t ah_base = smem_u32(Ah);
    uint32_t al_base = smem_u32(Al);
    uint32_t bh_base = smem_u32(Bh);
    uint32_t bl_base = smem_u32(Bl);

    const uint4* s;
    s = (const uint4*)(pAh); dAh[0] = s[0]; dAh[1] = s[1];
    s = (const uint4*)(pAl); dAl[0] = s[0]; dAl[1] = s[1];
    s = (const uint4*)(pBh); dBh[0] = s[0]; dBh[1] = s[1];
    s = (const uint4*)(pBl); dBl[0] = s[0]; dBl[1] = s[1];
    __syncthreads();

    int T = C/KC;
    for (int kc = 0; kc < T; kc++){
        uint4 rf[8];
        if (kc+1 < T){
            s = (const uint4*)(pAh + (kc+1)*KC); rf[0] = s[0]; rf[1] = s[1];
            s = (const uint4*)(pAl + (kc+1)*KC); rf[2] = s[0]; rf[3] = s[1];
            s = (const uint4*)(pBh + (kc+1)*KC); rf[4] = s[0]; rf[5] = s[1];
            s = (const uint4*)(pBl + (kc+1)*KC); rf[6] = s[0]; rf[7] = s[1];
        }
        #pragma unroll
        for (int ks = 0; ks < 2; ks++){
            int kk = ks*16;
            int g = lane >> 3, r = lane & 7;
            uint32_t ahf[4][4], alf[4][4];
            #pragma unroll
            for (int mi = 0; mi < 4; mi++){
                int arow = wm*64 + mi*16 + (g & 1)*8 + r;
                uint32_t off = (uint32_t)(arow*ASTRIDE + kk + (g >> 1)*8)*2u;
                ldm_x4(ahf[mi], ah_base + off);
                ldm_x4(alf[mi], al_base + off);
            }
            uint32_t bhf[2][4], blf[2][4];
            #pragma unroll
            for (int pr = 0; pr < 2; pr++){
                int nrow = wn*32 + pr*16 + (g >> 1)*8 + r;
                uint32_t off = (uint32_t)(nrow*ASTRIDE + kk + (g & 1)*8)*2u;
                ldm_x4(bhf[pr], bh_base + off);
                ldm_x4(blf[pr], bl_base + off);
            }
            #pragma unroll
            for (int mi = 0; mi < 4; mi++)
                #pragma unroll
                for (int ni = 0; ni < 4; ni++){
                    const uint32_t* bh2 = &bhf[ni >> 1][(ni & 1)*2];
                    const uint32_t* bl2 = &blf[ni >> 1][(ni & 1)*2];
                    mma_bf16(acc[mi][ni], ahf[mi], bh2);
                    mma_bf16(acc[mi][ni], ahf[mi], bl2);
                    mma_bf16(acc[mi][ni], alf[mi], bh2);
                }
        }
        __syncthreads();
        if (kc+1 < T){
            dAh[0] = rf[0]; dAh[1] = rf[1];
            dAl[0] = rf[2]; dAl[1] = rf[3];
            dBh[0] = rf[4]; dBh[1] = rf[5];
            dBl[0] = rf[6]; dBl[1] = rf[7];
            __syncthreads();
        }
    }

    // epilogue: keys for tile + mirror
    const float* xxb = g_xx + b*NPTS;
    unsigned* Db = g_key + (size_t)b*NPTS*NPTS;
    int rq = lane >> 2, cq = 2*(lane & 3);
    #pragma unroll
    for (int mi = 0; mi < 4; mi++){
        int rl0 = wm*64 + mi*16 + rq;
        float xr0 = xxb[row0 + rl0], xr1 = xxb[row0 + rl0 + 8];
        #pragma unroll
        for (int ni = 0; ni < 4; ni++){
            int cl0 = wn*32 + ni*8 + cq;
            float xc0 = xxb[col0 + cl0], xc1 = xxb[col0 + cl0 + 1];
            float a00 = 2.f*acc[mi][ni][0], a01 = 2.f*acc[mi][ni][1];
            float a10 = 2.f*acc[mi][ni][2], a11 = 2.f*acc[mi][ni][3];
            uint2 t0 = make_uint2(dist_key(a00 - xr0 - xc0), dist_key(a01 - xr0 - xc1));
            uint2 t1 = make_uint2(dist_key(a10 - xr1 - xc0), dist_key(a11 - xr1 - xc1));
            *(uint2*)&Db[(size_t)(row0 + rl0    )*NPTS + col0 + cl0] = t0;
            *(uint2*)&Db[(size_t)(row0 + rl0 + 8)*NPTS + col0 + cl0] = t1;
            if (bx != by){
                Db[(size_t)(col0 + cl0    )*NPTS + row0 + rl0    ] = dist_key(a00 - xc0 - xr0);
                Db[(size_t)(col0 + cl0 + 1)*NPTS + row0 + rl0    ] = dist_key(a01 - xc1 - xr0);
                Db[(size_t)(col0 + cl0    )*NPTS + row0 + rl0 + 8] = dist_key(a10 - xc0 - xr1);
                Db[(size_t)(col0 + cl0 + 1)*NPTS + row0 + rl0 + 8] = dist_key(a11 - xc1 - xr1);
            }
        }
    }
}

// ---------------- single-warp suffix scan over 256 bins + bucket pick ----------------
__device__ __forceinline__ void radix_pick(const int* hist, int r, int* sh_b, int* sh_r){
    int lane = threadIdx.x;
    int loc[8]; int tot = 0;
    #pragma unroll
    for (int q = 0; q < 8; q++){ loc[q] = hist[lane*8 + q]; tot += loc[q]; }
    int s = tot;
    #pragma unroll
    for (int off = 1; off < 32; off <<= 1){
        int v = __shfl_down_sync(0xffffffffu, s, off);
        if (lane + off < 32) s += v;
    }
    int run = s - tot;
    #pragma unroll
    for (int q = 7; q >= 0; q--){
        run += loc[q];
        if (run >= r && run - loc[q] < r){ *sh_b = lane*8 + q; *sh_r = r - (run - loc[q]); }
    }
}

// ---------------- top-k=20: register-resident u32 keys, 2-pass radix, exact tie refine ----------------
#define TIE_CAP 256
__global__ void k_topk(){
    int i = blockIdx.x, b = blockIdx.y;
    const unsigned* row = g_key + ((size_t)b*NPTS + i)*NPTS;
    int tid = threadIdx.x;

    __shared__ int hist0[256];
    __shared__ int hist1[256];
    __shared__ int sh_b0, sh_r0, sh_b1, sh_r1;
    __shared__ int sh_cnt, sh_tiecnt;
    __shared__ unsigned tie_key[TIE_CAP];
    __shared__ int      tie_idx[TIE_CAP];

    unsigned key[8];
    *(uint4*)(key)   = ((const uint4*)row)[tid];
    *(uint4*)(key+4) = ((const uint4*)row)[tid + 256];

    hist0[tid] = 0; hist1[tid] = 0;
    if (tid == 0){ sh_cnt = 0; sh_tiecnt = 0; }
    __syncthreads();

    #pragma unroll
    for (int q = 0; q < 8; q++) atomicAdd(&hist0[key[q] >> 24], 1);
    __syncthreads();
    if (tid < 32) radix_pick(hist0, KNN, &sh_b0, &sh_r0);
    __syncthreads();
    unsigned hi = (unsigned)sh_b0;

    #pragma unroll
    for (int q = 0; q < 8; q++)
        if ((key[q] >> 24) == hi) atomicAdd(&hist1[(key[q] >> 16) & 255u], 1);
    __syncthreads();
    if (tid < 32) radix_pick(hist1, sh_r0, &sh_b1, &sh_r1);
    __syncthreads();

    unsigned T16 = (hi << 8) | (unsigned)sh_b1;
    int need_eq = sh_r1;
    int* out = g_idx + ((size_t)b*NPTS + i)*KNN;

    #pragma unroll
    for (int q = 0; q < 8; q++){
        unsigned k = key[q];
        unsigned t16 = k >> 16;
        int j = (q < 4) ? (tid*4 + q) : (1024 + tid*4 + q - 4);
        if (t16 > T16){
            int slot = atomicAdd(&sh_cnt, 1);
            out[slot] = b*NPTS + j;
        } else if (t16 == T16){
            int t = atomicAdd(&sh_tiecnt, 1);
            if (t < TIE_CAP){ tie_key[t] = k; tie_idx[t] = j; }
        }
    }
    __syncthreads();
    if (tid == 0){
        int base = sh_cnt;
        int tc = sh_tiecnt; if (tc > TIE_CAP) tc = TIE_CAP;
        for (int q = 0; q < need_eq && base + q < KNN; q++){
            unsigned bk = 0; int bidx = 1 << 30, bu = -1;
            for (int u = 0; u < tc; u++){
                int vi = tie_idx[u];
                if (vi < 0) continue;
                unsigned vk = tie_key[u];
                if (bu < 0 || vk > bk || (vk == bk && vi < bidx)){
                    bk = vk; bidx = vi; bu = u;
                }
            }
            out[base + q] = b*NPTS + bidx;
            tie_idx[bu] = -1;
        }
    }
}

// ---------------- layer-0 projection (C=3): exact fp32 ----------------
__global__ void k_proj(int use0, int in_off, int C, int O, const float* __restrict__ w){
    int ldx = use0 ? 3 : FEAT;
    const float* X = use0 ? g_xt0 : (g_fcat + in_off);

    __shared__ float As[16][68];
    __shared__ float B1[16][68];
    __shared__ float B2[16][68];
    int tx = threadIdx.x, ty = threadIdx.y, tid = ty*16 + tx;
    int row0 = blockIdx.y*64, col0 = blockIdx.x*64;
    int lm = tid >> 2, lk = (tid & 3) * 4;
    float a1[4][4] = {}, a2[4][4] = {};

    for (int k0 = 0; k0 < C; k0 += 16){
        #pragma unroll
        for (int i = 0; i < 4; i++){
            int k = lk + i;
            float a = 0.f, b1 = 0.f, b2 = 0.f;
            if (k0 + k < C){
                a  = X[(size_t)(row0+lm)*ldx + k0 + k];
                b1 = w[(size_t)(col0+lm)*2*C + k0 + k];
                b2 = w[(size_t)(col0+lm)*2*C + C + k0 + k];
            }
            As[k][lm] = a; B1[k][lm] = b1; B2[k][lm] = b2;
        }
        __syncthreads();
        #pragma unroll
        for (int k = 0; k < 16; k++){
            float av[4], v1[4], v2[4];
            #pragma unroll
            for (int i = 0; i < 4; i++) av[i] = As[k][ty*4+i];
            #pragma unroll
            for (int j = 0; j < 4; j++){ v1[j] = B1[k][tx*4+j]; v2[j] = B2[k][tx*4+j]; }
            #pragma unroll
            for (int i = 0; i < 4; i++)
                #pragma unroll
                for (int j = 0; j < 4; j++){
                    a1[i][j] += av[i]*v1[j];
                    a2[i][j] += av[i]*v2[j];
                }
        }
        __syncthreads();
    }
    #pragma unroll
    for (int i = 0; i < 4; i++){
        int r = row0 + ty*4 + i;
        #pragma unroll
        for (int j = 0; j < 4; j++){
            int c = col0 + tx*4 + j;
            g_P1[(size_t)r*O + c] = a1[i][j];
            g_P2[(size_t)r*O + c] = a2[i][j] - a1[i][j];
        }
    }
}

// ---------------- stacked proj weights: rows [0,O)=W1, [O,2O)=W2-W1; bf16 split ----------------
__global__ void k_prepw(const float* __restrict__ w, int C, int O){
    int t = blockIdx.x*256 + threadIdx.x;
    if (t >= 2*O*C) return;
    int row = t / C, col = t % C;
    float v;
    if (row < O) v = w[(size_t)row*2*C + col];
    else         v = w[(size_t)(row-O)*2*C + C + col] - w[(size_t)(row-O)*2*C + col];
    __nv_bfloat16 h = __float2bfloat16(v);
    g_pwhi[(size_t)row*C + col] = h;
    g_pwlo[(size_t)row*C + col] = __float2bfloat16(v - __bfloat162float(h));
}

// ---------------- proj layers 1-3 via bf16-split mma: P = X @ [W1; W2-W1]^T ----------------
__global__ void __launch_bounds__(256) k_proj_mma(int in_off, int C, int O){
    __shared__ __align__(16) __nv_bfloat16 Ah[128*ASTRIDE];
    __shared__ __align__(16) __nv_bfloat16 Al[128*ASTRIDE];
    __shared__ __align__(16) __nv_bfloat16 Bh[128*ASTRIDE];
    __shared__ __align__(16) __nv_bfloat16 Bl[128*ASTRIDE];

    int tid = threadIdx.x, wid = tid >> 5, lane = tid & 31;
    int col0 = blockIdx.x*128;
    int row0 = blockIdx.y*128;
    int wm = wid >> 2, wn = wid & 3;

    float acc[4][4][4];
    #pragma unroll
    for (int mi = 0; mi < 4; mi++)
        #pragma unroll
        for (int ni = 0; ni < 4; ni++)
            #pragma unroll
            for (int c = 0; c < 4; c++) acc[mi][ni][c] = 0.f;

    int lr = tid >> 1, ls = tid & 1;
    const __nv_bfloat16* pAh = g_fhi + (size_t)(row0 + lr)*FEAT + in_off + ls*16;
    const __nv_bfloat16* pAl = g_flo + (size_t)(row0 + lr)*FEAT + in_off + ls*16;
    const __nv_bfloat16* pBh = g_pwhi + (size_t)(col0 + lr)*C + ls*16;
    const __nv_bfloat16* pBl = g_pwlo + (size_t)(col0 + lr)*C + ls*16;
    uint4* dAh = (uint4*)&Ah[lr*ASTRIDE + ls*16];
    uint4* dAl = (uint4*)&Al[lr*ASTRIDE + ls*16];
    uint4* dBh = (uint4*)&Bh[lr*ASTRIDE + ls*16];
    uint4* dBl = (uint4*)&Bl[lr*ASTRIDE + ls*16];

    uint32_t ah_base = smem_u32(Ah);
    uint32_t al_base = smem_u32(Al);
    uint32_t bh_base = smem_u32(Bh);
    uint32_t bl_base = smem_u32(Bl);

    const uint4* s;
    s = (const uint4*)(pAh); dAh[0] = s[0]; dAh[1] = s[1];
    s = (const uint4*)(pAl); dAl[0] = s[0]; dAl[1] = s[1];
    s = (const uint4*)(pBh); dBh[0] = s[0]; dBh[1] = s[1];
    s = (const uint4*)(pBl); dBl[0] = s[0]; dBl[1] = s[1];
    __syncthreads();

    int T = C/KC;
    for (int kc = 0; kc < T; kc++){
        uint4 rf[8];
        if (kc+1 < T){
            s = (const uint4*)(pAh + (kc+1)*KC); rf[0] = s[0]; rf[1] = s[1];
            s = (const uint4*)(pAl + (kc+1)*KC); rf[2] = s[0]; rf[3] = s[1];
            s = (const uint4*)(pBh + (kc+1)*KC); rf[4] = s[0]; rf[5] = s[1];
            s = (const uint4*)(pBl + (kc+1)*KC); rf[6] = s[0]; rf[7] = s[1];
        }
        #pragma unroll
        for (int ks = 0; ks < 2; ks++){
            int kk = ks*16;
            int g = lane >> 3, r = lane & 7;
            uint32_t ahf[4][4], alf[4][4];
            #pragma unroll
            for (int mi = 0; mi < 4; mi++){
                int arow = wm*64 + mi*16 + (g & 1)*8 + r;
                uint32_t off = (uint32_t)(arow*ASTRIDE + kk + (g >> 1)*8)*2u;
                ldm_x4(ahf[mi], ah_base + off);
                ldm_x4(alf[mi], al_base + off);
            }
            uint32_t bhf[2][4], blf[2][4];
            #pragma unroll
            for (int pr = 0; pr < 2; pr++){
                int nrow = wn*32 + pr*16 + (g >> 1)*8 + r;
                uint32_t off = (uint32_t)(nrow*ASTRIDE + kk + (g & 1)*8)*2u;
                ldm_x4(bhf[pr], bh_base + off);
                ldm_x4(blf[pr], bl_base + off);
            }
            #pragma unroll
            for (int mi = 0; mi < 4; mi++)
                #pragma unroll
                for (int ni = 0; ni < 4; ni++){
                    const uint32_t* bh2 = &bhf[ni >> 1][(ni & 1)*2];
                    const uint32_t* bl2 = &blf[ni >> 1][(ni & 1)*2];
                    mma_bf16(acc[mi][ni], ahf[mi], bh2);
                    mma_bf16(acc[mi][ni], ahf[mi], bl2);
                    mma_bf16(acc[mi][ni], alf[mi], bh2);
                }
        }
        __syncthreads();
        if (kc+1 < T){
            dAh[0] = rf[0]; dAh[1] = rf[1];
            dAl[0] = rf[2]; dAl[1] = rf[3];
            dBh[0] = rf[4]; dBh[1] = rf[5];
            dBl[0] = rf[6]; dBl[1] = rf[7];
            __syncthreads();
        }
    }

    // epilogue: scatter into g_P1 (cols < O) / g_P2 (cols >= O)
    int rq = lane >> 2, cq = 2*(lane & 3);
    #pragma unroll
    for (int mi = 0; mi < 4; mi++){
        int rl0 = wm*64 + mi*16 + rq;
        int pt0 = row0 + rl0, pt1 = pt0 + 8;
        #pragma unroll
        for (int ni = 0; ni < 4; ni++){
            int cg = col0 + wn*32 + ni*8 + cq;
            float* dst0;
            float* dst1;
            if (cg < O){
                dst0 = &g_P1[(size_t)pt0*O + cg];
                dst1 = &g_P1[(size_t)pt1*O + cg];
            } else {
                dst0 = &g_P2[(size_t)pt0*O + cg - O];
                dst1 = &g_P2[(size_t)pt1*O + cg - O];
            }
            *(float2*)dst0 = make_float2(acc[mi][ni][0], acc[mi][ni][1]);
            *(float2*)dst1 = make_float2(acc[mi][ni][2], acc[mi][ni][3]);
        }
    }
}

// ---------------- gather-max + BN + lrelu -> fcat + bf16 split + fp16 + fused sqnorm ----------------
__global__ void k_gathermax(int O, int out_off, const float* __restrict__ bnp){
    int pt = blockIdx.x;
    int o  = threadIdx.x;
    int lane = o & 31, wid = o >> 5;
    float g  = bnp[o], be = bnp[O+o], m = bnp[2*O+o], v = bnp[3*O+o];
    float sc = g * rsqrtf(v + EPS);
    float p2 = g_P2[(size_t)pt*O + o];

    __shared__ int id[KNN];
    __shared__ float ssum[8];
    if (o < KNN) id[o] = g_idx[(size_t)pt*KNN + o];
    __syncthreads();

    float mx = -3e38f, mn = 3e38f;
    #pragma unroll
    for (int j = 0; j < KNN; j++){
        float val = g_P1[(size_t)id[j]*O + o];
        mx = fmaxf(mx, val);
        mn = fminf(mn, val);
    }
    float chosen = (sc >= 0.f) ? mx : mn;
    float z = (chosen + p2 - m)*sc + be;
    z = z >= 0.f ? z : 0.2f*z;
    size_t idx = (size_t)pt*FEAT + out_off + o;
    g_fcat[idx] = z;
    __nv_bfloat16 h = __float2bfloat16(z);
    g_fhi[idx] = h;
    g_flo[idx] = __float2bfloat16(z - __bfloat162float(h));
    g_f16[idx] = __float2half(z);

    // fused squared-norm of this slice (next layer's xx)
    float zz = z*z;
    #pragma unroll
    for (int off = 16; off; off >>= 1) zz += __shfl_down_sync(0xffffffffu, zz, off);
    if (lane == 0) ssum[wid] = zz;
    __syncthreads();
    if (o == 0){
        float ssx = ssum[0];
        int nw = O >> 5;
        for (int w = 1; w < nw; w++) ssx += ssum[w];
        g_xx[pt] = ssx;
    }
}

// ---------------- fp16 of w5 ----------------
__global__ void k_splitw(const float* __restrict__ w5){
    int t = blockIdx.x*256 + threadIdx.x;
    if (t >= 1024*FEAT) return;
    g_w516[t] = __float2half(w5[t]);
}

// ---------------- conv5 via single-product fp16 mma, reg prefetch ----------------
__global__ void __launch_bounds__(256) k_conv5_mma(const float* __restrict__ bn5){
    __shared__ __align__(16) __half Ah[128*ASTRIDE];
    __shared__ __align__(16) __half Bh[128*ASTRIDE];
    __shared__ float red_mx[128][4];
    __shared__ float red_sm[128][4];

    int tid = threadIdx.x, wid = tid >> 5, lane = tid & 31;
    int b = blockIdx.z;
    int row0 = blockIdx.y*128, col0 = blockIdx.x*128;
    int wm = wid >> 2, wn = wid & 3;

    float acc[4][4][4];
    #pragma unroll
    for (int mi = 0; mi < 4; mi++)
        #pragma unroll
        for (int ni = 0; ni < 4; ni++)
            #pragma unroll
            for (int c = 0; c < 4; c++) acc[mi][ni][c] = 0.f;

    int lr = tid >> 1, ls = tid & 1;
    const __half* pA = g_w516 + (size_t)(row0 + lr)*FEAT + ls*16;
    const __half* pB = g_f16 + ((size_t)b*NPTS + col0 + lr)*FEAT + ls*16;
    uint4* dA = (uint4*)&Ah[lr*ASTRIDE + ls*16];
    uint4* dB = (uint4*)&Bh[lr*ASTRIDE + ls*16];

    uint32_t a_base = smem_u32(Ah);
    uint32_t b_base = smem_u32(Bh);

    const uint4* s;
    s = (const uint4*)(pA); dA[0] = s[0]; dA[1] = s[1];
    s = (const uint4*)(pB); dB[0] = s[0]; dB[1] = s[1];
    __syncthreads();

    const int T = FEAT/KC;   // 16
    for (int kc = 0; kc < T; kc++){
        uint4 rf[4];
        if (kc+1 < T){
            s = (const uint4*)(pA + (kc+1)*KC); rf[0] = s[0]; rf[1] = s[1];
            s = (const uint4*)(pB + (kc+1)*KC); rf[2] = s[0]; rf[3] = s[1];
        }
        #pragma unroll
        for (int ks = 0; ks < 2; ks++){
            int kk = ks*16;
            int g = lane >> 3, r = lane & 7;
            uint32_t af[4][4];
            #pragma unroll
            for (int mi = 0; mi < 4; mi++){
                int arow = wm*64 + mi*16 + (g & 1)*8 + r;
                uint32_t off = (uint32_t)(arow*ASTRIDE + kk + (g >> 1)*8)*2u;
                ldm_x4(af[mi], a_base + off);
            }
            uint32_t bf[2][4];
            #pragma unroll
            for (int pr = 0; pr < 2; pr++){
                int nrow = wn*32 + pr*16 + (g >> 1)*8 + r;
                uint32_t off = (uint32_t)(nrow*ASTRIDE + kk + (g & 1)*8)*2u;
                ldm_x4(bf[pr], b_base + off);
            }
            #pragma unroll
            for (int mi = 0; mi < 4; mi++)
                #pragma unroll
                for (int ni = 0; ni < 4; ni++)
                    mma_f16(acc[mi][ni], af[mi], &bf[ni >> 1][(ni & 1)*2]);
        }
        __syncthreads();
        if (kc+1 < T){
            dA[0] = rf[0]; dA[1] = rf[1];
            dB[0] = rf[2]; dB[1] = rf[3];
            __syncthreads();
        }
    }

    // epilogue: BN + lrelu, per-row max/sum over this block's 128 columns
    #pragma unroll
    for (int mi = 0; mi < 4; mi++){
        #pragma unroll
        for (int half = 0; half < 2; half++){
            int lrow = wm*64 + mi*16 + (lane >> 2) + half*8;
            int o = row0 + lrow;
            float g = bn5[o], be = bn5[1024+o], mm = bn5[2048+o], vv = bn5[3072+o];
            float sc = g * rsqrtf(vv + EPS);
            float mx = -3e38f, sm = 0.f;
            #pragma unroll
            for (int ni = 0; ni < 4; ni++){
                float z0 = (acc[mi][ni][half*2+0] - mm)*sc + be;
                z0 = z0 >= 0.f ? z0 : 0.2f*z0;
                float z1 = (acc[mi][ni][half*2+1] - mm)*sc + be;
                z1 = z1 >= 0.f ? z1 : 0.2f*z1;
                mx = fmaxf(mx, fmaxf(z0, z1)); sm += z0 + z1;
            }
            mx = fmaxf(mx, __shfl_xor_sync(0xffffffffu, mx, 1));
            sm += __shfl_xor_sync(0xffffffffu, sm, 1);
            mx = fmaxf(mx, __shfl_xor_sync(0xffffffffu, mx, 2));
            sm += __shfl_xor_sync(0xffffffffu, sm, 2);
            if ((lane & 3) == 0){
                red_mx[lrow][wn] = mx;
                red_sm[lrow][wn] = sm;
            }
        }
    }
    __syncthreads();
    if (tid < 128){
        float mx = red_mx[tid][0], sm = red_sm[tid][0];
        #pragma unroll
        for (int q = 1; q < 4; q++){
            mx = fmaxf(mx, red_mx[tid][q]);
            sm += red_sm[tid][q];
        }
        int idx = (blockIdx.x*BATCH + b)*1024 + row0 + tid;
        g_pmax[idx] = mx;
        g_psum[idx] = sm;
    }
}

// ---------------- reduce partials -> pooled [max, mean] ----------------
__global__ void k_poolreduce(){
    int t = blockIdx.x*256 + threadIdx.x;
    if (t >= BATCH*1024) return;
    int b = t / 1024, o = t % 1024;
    float mx = -3e38f, sm = 0.f;
    #pragma unroll
    for (int nb = 0; nb < 16; nb++){
        int idx = (nb*BATCH + b)*1024 + o;
        mx = fmaxf(mx, g_pmax[idx]);
        sm += g_psum[idx];
    }
    g_pooled[b*2048 + o]        = mx;
    g_pooled[b*2048 + 1024 + o] = sm * (1.0f/NPTS);
}

// ---------------- head layer 1 ----------------
__global__ void k_head1(const float* __restrict__ lw1o, const float* __restrict__ bn6o,
                        const float* __restrict__ lw1n, const float* __restrict__ bn6n){
    int gw = (blockIdx.x*blockDim.x + threadIdx.x) >> 5;
    int lane = threadIdx.x & 31;
    if (gw >= 2*BATCH*512) return;
    int h = gw / (BATCH*512), r = gw % (BATCH*512);
    int b = r / 512, o = r & 511;
    const float* w  = (h ? lw1n : lw1o) + (size_t)o*2048;
    const float* bp =  h ? bn6n : bn6o;
    const float* p  = g_pooled + b*2048;
    float s = 0.f;
    for (int c = lane; c < 2048; c += 32) s += p[c]*w[c];
    #pragma unroll
    for (int off = 16; off; off >>= 1) s += __shfl_down_sync(0xffffffffu, s, off);
    if (lane == 0){
        float z = (s - bp[1024+o]) * bp[o] * rsqrtf(bp[1536+o] + EPS) + bp[512+o];
        g_h1[gw] = z >= 0.f ? z : 0.2f*z;
    }
}

// ---------------- head layer 2 ----------------
__global__ void k_head2(const float* __restrict__ lw2o, const float* __restrict__ lb2o,
                        const float* __restrict__ bn7o,
                        const float* __restrict__ lw2n, const float* __restrict__ lb2n,
                        const float* __restrict__ bn7n){
    int gw = (blockIdx.x*blockDim.x + threadIdx.x) >> 5;
    int lane = threadIdx.x & 31;
    if (gw >= 2*BATCH*256) return;
    int h = gw / (BATCH*256), r = gw % (BATCH*256);
    int b = r / 256, o = r & 255;
    const float* w  = (h ? lw2n : lw2o) + (size_t)o*512;
    const float* lb =  h ? lb2n : lb2o;
    const float* bp =  h ? bn7n : bn7o;
    const float* hh = g_h1 + h*BATCH*512 + b*512;
    float s = 0.f;
    for (int c = lane; c < 512; c += 32) s += hh[c]*w[c];
    #pragma unroll
    for (int off = 16; off; off >>= 1) s += __shfl_down_sync(0xffffffffu, s, off);
    if (lane == 0){
        s += lb[o];
        float z = (s - bp[512+o]) * bp[o] * rsqrtf(bp[768+o] + EPS) + bp[256+o];
        g_h2[gw] = z >= 0.f ? z : 0.2f*z;
    }
}

// ---------------- attribute class-weight matrices ----------------
__global__ void k_attW(const float* __restrict__ old_att, const float* __restrict__ attwo,
                       const float* __restrict__ attbo,
                       const float* __restrict__ new_att, const float* __restrict__ attwn,
                       const float* __restrict__ attbn){
    int gw = (blockIdx.x*blockDim.x + threadIdx.x) >> 5;
    int lane = threadIdx.x & 31;
    if (gw >= 50*256) return;
    const float *att, *aw, *ab;
    int a, o;
    if (gw < 40*256){ a = gw / 256; o = gw & 255; att = old_att; aw = attwo; ab = attbo; }
    else { int g2 = gw - 40*256; a = g2 / 256; o = g2 & 255; att = new_att; aw = attwn; ab = attbn; }
    float s = 0.f;
    for (int c = lane; c < 300; c += 32) s += att[a*300+c]*aw[o*300+c];
    #pragma unroll
    for (int off = 16; off; off >>= 1) s += __shfl_down_sync(0xffffffffu, s, off);
    if (lane == 0) g_W[gw] = fmaxf(0.f, s + ab[o]);
}

// ---------------- final ----------------
__global__ void k_final(float* __restrict__ out){
    int gw = (blockIdx.x*blockDim.x + threadIdx.x) >> 5;
    int lane = threadIdx.x & 31;
    if (gw >= 400) return;
    int h, b, a;
    const float* Wb;
    if (gw < 320){ h = 0; b = gw / 40; a = gw % 40; Wb = g_W + a*256; }
    else { int t = gw - 320; h = 1; b = t / 10; a = t % 10; Wb = g_W + 40*256 + a*256; }
    const float* hh = g_h2 + h*BATCH*256 + b*256;
    float s = 0.f;
    for (int c = lane; c < 256; c += 32) s += hh[c]*Wb[c];
    #pragma unroll
    for (int off = 16; off; off >>= 1) s += __shfl_down_sync(0xffffffffu, s, off);
    if (lane == 0) out[gw] = s;
}

// ---------------- launch ----------------
extern "C" void kernel_launch(void* const* d_in, const int* in_sizes, int n_in,
                              void* d_out, int out_size){
    const float* x        = (const float*)d_in[0];
    const float* old_att  = (const float*)d_in[1];
    const float* new_att  = (const float*)d_in[2];
    const float* w1       = (const float*)d_in[3];
    const float* w2       = (const float*)d_in[4];
    const float* w3       = (const float*)d_in[5];
    const float* w4       = (const float*)d_in[6];
    const float* w5       = (const float*)d_in[7];
    const float* bn1      = (const float*)d_in[8];
    const float* bn2      = (const float*)d_in[9];
    const float* bn3      = (const float*)d_in[10];
    const float* bn4      = (const float*)d_in[11];
    const float* bn5      = (const float*)d_in[12];
    const float* lw1_old  = (const float*)d_in[13];
    const float* bn6_old  = (const float*)d_in[14];
    const float* lw2_old  = (const float*)d_in[15];
    const float* lb2_old  = (const float*)d_in[16];
    const float* bn7_old  = (const float*)d_in[17];
    const float* lw1_new  = (const float*)d_in[18];
    const float* bn6_new  = (const float*)d_in[19];
    const float* lw2_new  = (const float*)d_in[20];
    const float* lb2_new  = (const float*)d_in[21];
    const float* bn7_new  = (const float*)d_in[22];
    const float* attw_old = (const float*)d_in[23];
    const float* attb_old = (const float*)d_in[24];
    const float* attw_new = (const float*)d_in[25];
    const float* attb_new = (const float*)d_in[26];

    dim3 t16(16, 16);

    k_prep<<<(TOTPTS+255)/256, 256>>>(x);

    struct Layer { int use0, in_off, C, O, out_off; const float *w, *bn; };
    Layer L[4] = {
        {1,   0,   3,  64,   0, w1, bn1},
        {0,   0,  64,  64,  64, w2, bn2},
        {0,  64,  64, 128, 128, w3, bn3},
        {0, 128, 128, 256, 256, w4, bn4},
    };

    for (int l = 0; l < 4; l++){
        if (L[l].use0)
            k_dist_small<<<dim3(NPTS/64, NPTS/64, BATCH), t16>>>();
        else
            k_dist_mma<<<dim3(136, 1, BATCH), 256>>>(L[l].in_off, L[l].C);
        k_topk<<<dim3(NPTS, BATCH), 256>>>();
        if (L[l].use0){
            k_proj<<<dim3(L[l].O/64, TOTPTS/64), t16>>>(L[l].use0, L[l].in_off, L[l].C, L[l].O, L[l].w);
        } else {
            int C = L[l].C, O = L[l].O;
            k_prepw<<<(2*O*C + 255)/256, 256>>>(L[l].w, C, O);
            k_proj_mma<<<dim3(2*O/128, TOTPTS/128), 256>>>(L[l].in_off, C, O);
        }
        k_gathermax<<<TOTPTS, L[l].O>>>(L[l].O, L[l].out_off, L[l].bn);
    }

    k_splitw<<<(1024*FEAT)/256, 256>>>(w5);
    k_conv5_mma<<<dim3(NPTS/128, 1024/128, BATCH), 256>>>(bn5);
    k_poolreduce<<<(BATCH*1024 + 255)/256, 256>>>();
    k_head1<<<(2*BATCH*512*32)/256, 256>>>(lw1_old, bn6_old, lw1_new, bn6_new);
    k_head2<<<(2*BATCH*256*32)/256, 256>>>(lw2_old, lb2_old, bn7_old, lw2_new, lb2_new, bn7_new);
    k_attW<<<(50*256*32)/256, 256>>>(old_att, attw_old, attb_old, new_att, attw_new, attb_new);
    k_final<<<(400*32 + 255)/256, 256>>>((float*)d_out);
}